// round 2
// baseline (speedup 1.0000x reference)
#include <cuda_runtime.h>
#include <cuda_bf16.h>
#include <math.h>

#define DIMK 1024
#define CC   128
#define BB   8
#define TT   2048
#define ROWS (BB*TT)   // 16384

// ------------------------- device scratch (no allocs allowed) -------------
__device__ float g_Q [ROWS*CC];
__device__ float g_K [ROWS*CC];   // normalized k
__device__ float g_V [ROWS*CC];
__device__ float g_G [ROWS*CC];
__device__ float g_O [ROWS*CC];
__device__ float g_Al[ROWS];
__device__ float g_Be[ROWS];

__device__ __forceinline__ float sigmoidf_(float x) { return 1.0f / (1.0f + expf(-x)); }

// ===========================================================================
// Kernel 1: projections  q,k,v,g = x @ W + b   (grid: 128 M-tiles x 4 mats)
// SGEMM: BM=128, BN=128, BK=16, TM=TN=8, 256 threads
// ===========================================================================
__global__ __launch_bounds__(256) void proj_gemm(
    const float* __restrict__ x,
    const float* __restrict__ Wq, const float* __restrict__ Wk,
    const float* __restrict__ Wv, const float* __restrict__ Wg,
    const float* __restrict__ bq, const float* __restrict__ bk,
    const float* __restrict__ bv, const float* __restrict__ bg)
{
    __shared__ float As[16][128];
    __shared__ float Bs[16][128];

    const int mid  = blockIdx.y;
    const float* W    = (mid == 0) ? Wq : (mid == 1) ? Wk : (mid == 2) ? Wv : Wg;
    const float* bias = (mid == 0) ? bq : (mid == 1) ? bk : (mid == 2) ? bv : bg;
    float* outp       = (mid == 0) ? g_Q : (mid == 1) ? g_K : (mid == 2) ? g_V : g_G;

    const int row0 = blockIdx.x * 128;
    const int tid  = threadIdx.x;
    const int tx   = tid & 15;       // 0..15 col group
    const int ty   = tid >> 4;       // 0..15 row group

    const int lr = tid >> 2;         // 0..63
    const int lc = (tid & 3) * 4;    // 0,4,8,12

    float acc[8][8];
#pragma unroll
    for (int m = 0; m < 8; ++m)
#pragma unroll
        for (int n = 0; n < 8; ++n) acc[m][n] = 0.0f;

    for (int k0 = 0; k0 < DIMK; k0 += 16) {
#pragma unroll
        for (int h = 0; h < 2; ++h) {
            int r = lr + h * 64;
            float4 a4 = *(const float4*)(x + (size_t)(row0 + r) * DIMK + k0 + lc);
            As[lc + 0][r] = a4.x; As[lc + 1][r] = a4.y;
            As[lc + 2][r] = a4.z; As[lc + 3][r] = a4.w;
        }
#pragma unroll
        for (int h = 0; h < 2; ++h) {
            int kk = (tid >> 5) + h * 8;
            int n  = (tid & 31) * 4;
            float4 b4 = *(const float4*)(W + (size_t)(k0 + kk) * CC + n);
            *(float4*)&Bs[kk][n] = b4;
        }
        __syncthreads();
#pragma unroll
        for (int kk = 0; kk < 16; ++kk) {
            float ar[8], br[8];
            *(float4*)&ar[0] = *(float4*)&As[kk][ty * 8];
            *(float4*)&ar[4] = *(float4*)&As[kk][ty * 8 + 4];
            *(float4*)&br[0] = *(float4*)&Bs[kk][tx * 8];
            *(float4*)&br[4] = *(float4*)&Bs[kk][tx * 8 + 4];
#pragma unroll
            for (int m = 0; m < 8; ++m)
#pragma unroll
                for (int n = 0; n < 8; ++n)
                    acc[m][n] = fmaf(ar[m], br[n], acc[m][n]);
        }
        __syncthreads();
    }

#pragma unroll
    for (int m = 0; m < 8; ++m) {
        int row = row0 + ty * 8 + m;
#pragma unroll
        for (int n = 0; n < 8; ++n) {
            int col = tx * 8 + n;
            float v = acc[m][n] + bias[col];
            if (mid == 3) v = sigmoidf_(v);            // gate
            outp[(size_t)row * CC + col] = v;
        }
    }
}

// ===========================================================================
// Kernel 2: alpha/beta = sigmoid(x @ Wa + ba), sigmoid(x @ Wb + bb)
// one warp per row, 8 warps/block, grid 2048
// ===========================================================================
__global__ __launch_bounds__(256) void ab_kernel(
    const float* __restrict__ x,
    const float* __restrict__ Wa, const float* __restrict__ ba,
    const float* __restrict__ Wb, const float* __restrict__ bb)
{
    const int warp = threadIdx.x >> 5, lane = threadIdx.x & 31;
    const int row  = blockIdx.x * 8 + warp;
    const float* xr = x + (size_t)row * DIMK;
    float accA = 0.0f, accB = 0.0f;
#pragma unroll
    for (int it = 0; it < 8; ++it) {
        int kidx = it * 128 + lane * 4;
        float4 xv = *(const float4*)(xr + kidx);
        float4 wa = *(const float4*)(Wa + kidx);
        float4 wb = *(const float4*)(Wb + kidx);
        accA += xv.x * wa.x + xv.y * wa.y + xv.z * wa.z + xv.w * wa.w;
        accB += xv.x * wb.x + xv.y * wb.y + xv.z * wb.z + xv.w * wb.w;
    }
#pragma unroll
    for (int o = 16; o; o >>= 1) {
        accA += __shfl_xor_sync(0xffffffffu, accA, o);
        accB += __shfl_xor_sync(0xffffffffu, accB, o);
    }
    if (lane == 0) {
        g_Al[row] = sigmoidf_(accA + ba[0]);
        g_Be[row] = sigmoidf_(accB + bb[0]);
    }
}

// ===========================================================================
// Kernel 3: normalize k rows: k = kr / max(||kr||, 1e-12)
// ===========================================================================
__global__ __launch_bounds__(256) void knorm_kernel()
{
    const int warp = threadIdx.x >> 5, lane = threadIdx.x & 31;
    const int row  = blockIdx.x * 8 + warp;
    float* kp = g_K + (size_t)row * CC + lane * 4;
    float4 kv = *(float4*)kp;
    float ss = kv.x * kv.x + kv.y * kv.y + kv.z * kv.z + kv.w * kv.w;
#pragma unroll
    for (int o = 16; o; o >>= 1) ss += __shfl_xor_sync(0xffffffffu, ss, o);
    float scale = 1.0f / fmaxf(sqrtf(ss), 1e-12f);
    kv.x *= scale; kv.y *= scale; kv.z *= scale; kv.w *= scale;
    *(float4*)kp = kv;
}

// ===========================================================================
// Kernel 4: sequential gated-delta scan, one CTA per batch.
// 256 threads: t<128 holds row i of S (in regs), t>=128 holds row j of S^T.
// S is stored scaled: S_true = c * S_hat (c block-uniform), so the rank-1
// update is a single FMA per element. Rescale when c < 1e-10.
// ===========================================================================
__global__ __launch_bounds__(256, 1) void scan_kernel()
{
    const int b    = blockIdx.x;
    const int tid  = threadIdx.x;
    const int lane = tid & 31, warp = tid >> 5;
    const bool isA = (tid < 128);
    const int  r   = isA ? tid : (tid - 128);

    __shared__ float k_sh[128], q_sh[128], v_sh[128], g_sh[128], u_sh[128];
    __shared__ float qup[4];
    __shared__ float ab_sh[2];

    float S[128];
#pragma unroll
    for (int j = 0; j < 128; ++j) S[j] = 0.0f;
    float c = 1.0f;

    const size_t base = (size_t)b * TT * CC;
    const float* Qb = g_Q + base;
    const float* Kb = g_K + base;
    const float* Vb = g_V + base;
    const float* Gb = g_G + base;
    const float* Ab = g_Al + (size_t)b * TT;
    const float* Bb = g_Be + (size_t)b * TT;
    float*       Ob = g_O + base;

    for (int t = 0; t < TT; ++t) {
        if (isA) { k_sh[r] = Kb[t * CC + r]; q_sh[r] = Qb[t * CC + r]; }
        else     { v_sh[r] = Vb[t * CC + r]; g_sh[r] = Gb[t * CC + r]; }
        if (tid == 0) { ab_sh[0] = Ab[t]; ab_sh[1] = Bb[t]; }
        __syncthreads();

        const float aa = ab_sh[0], bbv = ab_sh[1];
        float u = 0.0f, phat = 0.0f;

        if (isA) {
            // Sk_hat = S_hat[i,:] . k
            float a0 = 0.f, a1 = 0.f, a2 = 0.f, a3 = 0.f;
            const float4* k4 = (const float4*)k_sh;
#pragma unroll
            for (int j = 0; j < 32; ++j) {
                float4 kk = k4[j];
                a0 = fmaf(S[4 * j + 0], kk.x, a0);
                a1 = fmaf(S[4 * j + 1], kk.y, a1);
                a2 = fmaf(S[4 * j + 2], kk.z, a2);
                a3 = fmaf(S[4 * j + 3], kk.w, a3);
            }
            float Sk = c * ((a0 + a1) + (a2 + a3));
            u = bbv * v_sh[r] - aa * bbv * Sk;
            u_sh[r] = u;
            float pq = q_sh[r] * u;
#pragma unroll
            for (int o = 16; o; o >>= 1) pq += __shfl_xor_sync(0xffffffffu, pq, o);
            if (lane == 0) qup[warp] = pq;
        } else {
            // phat_j = S_hat^T[j,:] . q  =  (q^T S_hat)[j]
            float a0 = 0.f, a1 = 0.f, a2 = 0.f, a3 = 0.f;
            const float4* q4 = (const float4*)q_sh;
#pragma unroll
            for (int j = 0; j < 32; ++j) {
                float4 qq = q4[j];
                a0 = fmaf(S[4 * j + 0], qq.x, a0);
                a1 = fmaf(S[4 * j + 1], qq.y, a1);
                a2 = fmaf(S[4 * j + 2], qq.z, a2);
                a3 = fmaf(S[4 * j + 3], qq.w, a3);
            }
            phat = (a0 + a1) + (a2 + a3);
        }
        __syncthreads();

        const float cn   = aa * c;
        const float winv = 1.0f / cn;

        if (isA) {
            // S_hat[i,j] += (u/cn) * k[j]
            const float w = u * winv;
            const float4* k4 = (const float4*)k_sh;
#pragma unroll
            for (int j = 0; j < 32; ++j) {
                float4 kk = k4[j];
                S[4 * j + 0] = fmaf(w, kk.x, S[4 * j + 0]);
                S[4 * j + 1] = fmaf(w, kk.y, S[4 * j + 1]);
                S[4 * j + 2] = fmaf(w, kk.z, S[4 * j + 2]);
                S[4 * j + 3] = fmaf(w, kk.w, S[4 * j + 3]);
            }
        } else {
            const float qu = qup[0] + qup[1] + qup[2] + qup[3];
            const float kj = k_sh[r];
            float o = aa * (c * phat) + qu * kj;       // o = q^T S_new
            Ob[t * CC + r] = o * g_sh[r];
            // S_hat^T[j,i] += (k[j]/cn) * u[i]
            const float kw = kj * winv;
            const float4* u4 = (const float4*)u_sh;
#pragma unroll
            for (int j = 0; j < 32; ++j) {
                float4 uu = u4[j];
                S[4 * j + 0] = fmaf(kw, uu.x, S[4 * j + 0]);
                S[4 * j + 1] = fmaf(kw, uu.y, S[4 * j + 1]);
                S[4 * j + 2] = fmaf(kw, uu.z, S[4 * j + 2]);
                S[4 * j + 3] = fmaf(kw, uu.w, S[4 * j + 3]);
            }
        }

        c = cn;
        if (c < 1e-10f) {
#pragma unroll
            for (int j = 0; j < 128; ++j) S[j] *= c;
            c = 1.0f;
        }
        __syncthreads();
    }
}

// ===========================================================================
// Kernel 5: out = O @ Wo + bo   (M=16384, N=1024, K=128)
// grid: (128 M-tiles, 8 N-tiles)
// ===========================================================================
__global__ __launch_bounds__(256) void out_gemm(
    const float* __restrict__ Wo, const float* __restrict__ bo,
    float* __restrict__ out)
{
    __shared__ float As[16][128];
    __shared__ float Bs[16][128];

    const int row0 = blockIdx.x * 128;
    const int col0 = blockIdx.y * 128;
    const int tid  = threadIdx.x;
    const int tx   = tid & 15;
    const int ty   = tid >> 4;
    const int lr   = tid >> 2;
    const int lc   = (tid & 3) * 4;

    float acc[8][8];
#pragma unroll
    for (int m = 0; m < 8; ++m)
#pragma unroll
        for (int n = 0; n < 8; ++n) acc[m][n] = 0.0f;

    for (int k0 = 0; k0 < CC; k0 += 16) {
#pragma unroll
        for (int h = 0; h < 2; ++h) {
            int r = lr + h * 64;
            float4 a4 = *(const float4*)(g_O + (size_t)(row0 + r) * CC + k0 + lc);
            As[lc + 0][r] = a4.x; As[lc + 1][r] = a4.y;
            As[lc + 2][r] = a4.z; As[lc + 3][r] = a4.w;
        }
#pragma unroll
        for (int h = 0; h < 2; ++h) {
            int kk = (tid >> 5) + h * 8;
            int n  = (tid & 31) * 4;
            float4 b4 = *(const float4*)(Wo + (size_t)(k0 + kk) * DIMK + col0 + n);
            *(float4*)&Bs[kk][n] = b4;
        }
        __syncthreads();
#pragma unroll
        for (int kk = 0; kk < 16; ++kk) {
            float ar[8], br[8];
            *(float4*)&ar[0] = *(float4*)&As[kk][ty * 8];
            *(float4*)&ar[4] = *(float4*)&As[kk][ty * 8 + 4];
            *(float4*)&br[0] = *(float4*)&Bs[kk][tx * 8];
            *(float4*)&br[4] = *(float4*)&Bs[kk][tx * 8 + 4];
#pragma unroll
            for (int m = 0; m < 8; ++m)
#pragma unroll
                for (int n = 0; n < 8; ++n)
                    acc[m][n] = fmaf(ar[m], br[n], acc[m][n]);
        }
        __syncthreads();
    }

#pragma unroll
    for (int m = 0; m < 8; ++m) {
        int row = row0 + ty * 8 + m;
#pragma unroll
        for (int n = 0; n < 8; ++n) {
            int col = col0 + tx * 8 + n;
            out[(size_t)row * DIMK + col] = acc[m][n] + bo[col];
        }
    }
}

// ===========================================================================
extern "C" void kernel_launch(void* const* d_in, const int* in_sizes, int n_in,
                              void* d_out, int out_size)
{
    const float* x  = (const float*)d_in[0];
    const float* Wq = (const float*)d_in[1];  const float* bq = (const float*)d_in[2];
    const float* Wk = (const float*)d_in[3];  const float* bk = (const float*)d_in[4];
    const float* Wv = (const float*)d_in[5];  const float* bv = (const float*)d_in[6];
    const float* Wa = (const float*)d_in[7];  const float* ba = (const float*)d_in[8];
    const float* Wb = (const float*)d_in[9];  const float* bb = (const float*)d_in[10];
    const float* Wg = (const float*)d_in[11]; const float* bg = (const float*)d_in[12];
    const float* Wo = (const float*)d_in[13]; const float* bo = (const float*)d_in[14];
    float* out = (float*)d_out;

    proj_gemm<<<dim3(128, 4), 256>>>(x, Wq, Wk, Wv, Wg, bq, bk, bv, bg);
    ab_kernel<<<2048, 256>>>(x, Wa, ba, Wb, bb);
    knorm_kernel<<<2048, 256>>>();
    scan_kernel<<<BB, 256>>>();
    out_gemm<<<dim3(128, 8), 256>>>(Wo, bo, out);
}

// round 3
// speedup vs baseline: 1.3834x; 1.3834x over previous
#include <cuda_runtime.h>
#include <cuda_bf16.h>
#include <math.h>

#define DIMK 1024
#define CC   128
#define BB   8
#define TT   2048
#define ROWS (BB*TT)   // 16384

typedef unsigned long long ull;

// ------------------------- device scratch (no allocs allowed) -------------
__device__ float g_Q [ROWS*CC];
__device__ float g_K [ROWS*CC];   // normalized k
__device__ float g_V [ROWS*CC];
__device__ float g_G [ROWS*CC];
__device__ float g_O [ROWS*CC];
__device__ float g_Al[ROWS];
__device__ float g_Be[ROWS];

__device__ __forceinline__ float sigmoidf_(float x) { return 1.0f / (1.0f + expf(-x)); }

// ---- packed f32x2 helpers (Blackwell: FFMA2 only via PTX fma.rn.f32x2) ----
__device__ __forceinline__ ull pack2(float lo, float hi) {
    ull r; asm("mov.b64 %0, {%1, %2};" : "=l"(r) : "f"(lo), "f"(hi)); return r;
}
__device__ __forceinline__ void unpack2(ull v, float& lo, float& hi) {
    asm("mov.b64 {%0, %1}, %2;" : "=f"(lo), "=f"(hi) : "l"(v));
}
__device__ __forceinline__ ull fma2(ull a, ull b, ull c) {
    ull d; asm("fma.rn.f32x2 %0, %1, %2, %3;" : "=l"(d) : "l"(a), "l"(b), "l"(c)); return d;
}
__device__ __forceinline__ ull mul2(ull a, ull b) {
    ull d; asm("mul.rn.f32x2 %0, %1, %2;" : "=l"(d) : "l"(a), "l"(b)); return d;
}

// ===========================================================================
// Kernel 1: projections  q,k,v,g = x @ W + b   (grid: 128 M-tiles x 4 mats)
// f32x2 SGEMM: BM=128, BN=128, BK=16, TM=8, TN=8 (4 packed pairs), 256 thr
// A tile stored duplicated: As2[kk][2r] = As2[kk][2r+1] = A[r][kk]
// ===========================================================================
__global__ __launch_bounds__(256) void proj_gemm(
    const float* __restrict__ x,
    const float* __restrict__ Wq, const float* __restrict__ Wk,
    const float* __restrict__ Wv, const float* __restrict__ Wg,
    const float* __restrict__ bq, const float* __restrict__ bk,
    const float* __restrict__ bv, const float* __restrict__ bg)
{
    __shared__ __align__(16) float As2[16][256];
    __shared__ __align__(16) float Bs[16][128];

    const int mid  = blockIdx.y;
    const float* W    = (mid == 0) ? Wq : (mid == 1) ? Wk : (mid == 2) ? Wv : Wg;
    const float* bias = (mid == 0) ? bq : (mid == 1) ? bk : (mid == 2) ? bv : bg;
    float* outp       = (mid == 0) ? g_Q : (mid == 1) ? g_K : (mid == 2) ? g_V : g_G;

    const int row0 = blockIdx.x * 128;
    const int tid  = threadIdx.x;
    const int tx   = tid & 15;       // 0..15 col group (8 cols = 4 pairs)
    const int ty   = tid >> 4;       // 0..15 row group (8 rows)
    const int lr   = tid >> 2;       // 0..63
    const int lc   = (tid & 3) * 4;  // 0,4,8,12

    ull acc[8][4];
#pragma unroll
    for (int m = 0; m < 8; ++m)
#pragma unroll
        for (int n = 0; n < 4; ++n) acc[m][n] = 0ull;

    for (int k0 = 0; k0 < DIMK; k0 += 16) {
#pragma unroll
        for (int h = 0; h < 2; ++h) {
            int r = lr + h * 64;
            float4 a4 = *(const float4*)(x + (size_t)(row0 + r) * DIMK + k0 + lc);
            *(float2*)&As2[lc + 0][2 * r] = make_float2(a4.x, a4.x);
            *(float2*)&As2[lc + 1][2 * r] = make_float2(a4.y, a4.y);
            *(float2*)&As2[lc + 2][2 * r] = make_float2(a4.z, a4.z);
            *(float2*)&As2[lc + 3][2 * r] = make_float2(a4.w, a4.w);
        }
#pragma unroll
        for (int h = 0; h < 2; ++h) {
            int kk = (tid >> 5) + h * 8;
            int n  = (tid & 31) * 4;
            *(float4*)&Bs[kk][n] = *(const float4*)(W + (size_t)(k0 + kk) * CC + n);
        }
        __syncthreads();
#pragma unroll
        for (int kk = 0; kk < 16; ++kk) {
            const ulonglong2* ap = (const ulonglong2*)&As2[kk][2 * (ty * 8)];
            const ulonglong2* bp = (const ulonglong2*)&Bs[kk][tx * 8];
            ulonglong2 a01 = ap[0], a23 = ap[1], a45 = ap[2], a67 = ap[3];
            ulonglong2 b01 = bp[0], b23 = bp[1];
            ull ar[8] = {a01.x, a01.y, a23.x, a23.y, a45.x, a45.y, a67.x, a67.y};
            ull br[4] = {b01.x, b01.y, b23.x, b23.y};
#pragma unroll
            for (int m = 0; m < 8; ++m)
#pragma unroll
                for (int n = 0; n < 4; ++n)
                    acc[m][n] = fma2(ar[m], br[n], acc[m][n]);
        }
        __syncthreads();
    }

#pragma unroll
    for (int m = 0; m < 8; ++m) {
        int row = row0 + ty * 8 + m;
#pragma unroll
        for (int n = 0; n < 4; ++n) {
            int col = tx * 8 + 2 * n;
            float e0, e1; unpack2(acc[m][n], e0, e1);
            float v0 = e0 + bias[col];
            float v1 = e1 + bias[col + 1];
            if (mid == 3) { v0 = sigmoidf_(v0); v1 = sigmoidf_(v1); }
            *(float2*)&outp[(size_t)row * CC + col] = make_float2(v0, v1);
        }
    }
}

// ===========================================================================
// Kernel 2: alpha/beta = sigmoid(x @ Wa + ba), sigmoid(x @ Wb + bb)
// ===========================================================================
__global__ __launch_bounds__(256) void ab_kernel(
    const float* __restrict__ x,
    const float* __restrict__ Wa, const float* __restrict__ ba,
    const float* __restrict__ Wb, const float* __restrict__ bb)
{
    const int warp = threadIdx.x >> 5, lane = threadIdx.x & 31;
    const int row  = blockIdx.x * 8 + warp;
    const float* xr = x + (size_t)row * DIMK;
    float accA = 0.0f, accB = 0.0f;
#pragma unroll
    for (int it = 0; it < 8; ++it) {
        int kidx = it * 128 + lane * 4;
        float4 xv = *(const float4*)(xr + kidx);
        float4 wa = *(const float4*)(Wa + kidx);
        float4 wb = *(const float4*)(Wb + kidx);
        accA += xv.x * wa.x + xv.y * wa.y + xv.z * wa.z + xv.w * wa.w;
        accB += xv.x * wb.x + xv.y * wb.y + xv.z * wb.z + xv.w * wb.w;
    }
#pragma unroll
    for (int o = 16; o; o >>= 1) {
        accA += __shfl_xor_sync(0xffffffffu, accA, o);
        accB += __shfl_xor_sync(0xffffffffu, accB, o);
    }
    if (lane == 0) {
        g_Al[row] = sigmoidf_(accA + ba[0]);
        g_Be[row] = sigmoidf_(accB + bb[0]);
    }
}

// ===========================================================================
// Kernel 3: normalize k rows
// ===========================================================================
__global__ __launch_bounds__(256) void knorm_kernel()
{
    const int warp = threadIdx.x >> 5, lane = threadIdx.x & 31;
    const int row  = blockIdx.x * 8 + warp;
    float* kp = g_K + (size_t)row * CC + lane * 4;
    float4 kv = *(float4*)kp;
    float ss = kv.x * kv.x + kv.y * kv.y + kv.z * kv.z + kv.w * kv.w;
#pragma unroll
    for (int o = 16; o; o >>= 1) ss += __shfl_xor_sync(0xffffffffu, ss, o);
    float scale = 1.0f / fmaxf(sqrtf(ss), 1e-12f);
    kv.x *= scale; kv.y *= scale; kv.z *= scale; kv.w *= scale;
    *(float4*)kp = kv;
}

// ===========================================================================
// Kernel 4: sequential gated-delta scan, one CTA per batch.
// 256 threads: t<128 hold row i of S_hat, t>=128 hold row j of S_hat^T,
// all state packed f32x2 (64 ull regs). S_true = c * S_hat (c uniform).
// Double-buffered staging + register prefetch: 2 syncs/step, LDG hidden.
// ===========================================================================
__global__ __launch_bounds__(256, 1) void scan_kernel()
{
    const int b    = blockIdx.x;
    const int tid  = threadIdx.x;
    const int lane = tid & 31, warp = tid >> 5;
    const bool isA = (tid < 128);
    const int  r   = isA ? tid : (tid - 128);

    __shared__ __align__(16) float k_sh[2][128], q_sh[2][128];
    __shared__ __align__(16) float v_sh[2][128], g_sh[2][128];
    __shared__ __align__(16) float u_sh[128];
    __shared__ float qup[4];
    __shared__ float2 ab_sh[2];

    ull Sp[64];
#pragma unroll
    for (int j = 0; j < 64; ++j) Sp[j] = 0ull;
    float c = 1.0f;

    const size_t base = (size_t)b * TT * CC;
    const float* Qb = g_Q + base;
    const float* Kb = g_K + base;
    const float* Vb = g_V + base;
    const float* Gb = g_G + base;
    const float* Ab = g_Al + (size_t)b * TT;
    const float* Bb = g_Be + (size_t)b * TT;
    float*       Ob = g_O + base;

    // preload t=0
    float s0, s1;
    if (isA) { s0 = Kb[r]; s1 = Qb[r]; }
    else     { s0 = Vb[r]; s1 = Gb[r]; }
    float2 abr = make_float2(0.f, 0.f);
    if (tid == 0) abr = make_float2(Ab[0], Bb[0]);

    int p = 0;
    for (int t = 0; t < TT; ++t) {
        // stage into buffer p
        if (isA) { k_sh[p][r] = s0; q_sh[p][r] = s1; }
        else     { v_sh[p][r] = s0; g_sh[p][r] = s1; }
        if (tid == 0) ab_sh[p] = abr;
        __syncthreads();

        // prefetch t+1 (latency hides under the FMA2 chains below)
        if (t + 1 < TT) {
            const int off = (t + 1) * CC + r;
            if (isA) { s0 = Kb[off]; s1 = Qb[off]; }
            else     { s0 = Vb[off]; s1 = Gb[off]; }
            if (tid == 0) abr = make_float2(Ab[t + 1], Bb[t + 1]);
        }

        const float aa  = ab_sh[p].x;
        const float bbv = ab_sh[p].y;

        // packed dot: A threads vs k, B threads vs q
        const ulonglong2* x16 = (const ulonglong2*)(isA ? k_sh[p] : q_sh[p]);
        ull a0 = 0ull, a1 = 0ull, a2 = 0ull, a3 = 0ull;
#pragma unroll
        for (int j = 0; j < 16; ++j) {
            ulonglong2 xa = x16[2 * j], xb = x16[2 * j + 1];
            a0 = fma2(Sp[4 * j + 0], xa.x, a0);
            a1 = fma2(Sp[4 * j + 1], xa.y, a1);
            a2 = fma2(Sp[4 * j + 2], xb.x, a2);
            a3 = fma2(Sp[4 * j + 3], xb.y, a3);
        }
        float f0, f1, f2, f3, f4, f5, f6, f7;
        unpack2(a0, f0, f1); unpack2(a1, f2, f3);
        unpack2(a2, f4, f5); unpack2(a3, f6, f7);
        const float dot = ((f0 + f1) + (f2 + f3)) + ((f4 + f5) + (f6 + f7));

        float u = 0.0f, phat = 0.0f;
        if (isA) {
            const float Sk = c * dot;
            u = bbv * v_sh[p][r] - aa * bbv * Sk;
            u_sh[r] = u;
            float pq = q_sh[p][r] * u;
#pragma unroll
            for (int o = 16; o; o >>= 1) pq += __shfl_xor_sync(0xffffffffu, pq, o);
            if (lane == 0) qup[warp] = pq;
        } else {
            phat = dot;
        }
        __syncthreads();

        const float cn   = aa * c;
        const float winv = 1.0f / cn;

        if (isA) {
            // S_hat[i][:] += (u/cn) * k
            const ull w2 = pack2(u * winv, u * winv);
            const ulonglong2* k16 = (const ulonglong2*)k_sh[p];
#pragma unroll
            for (int j = 0; j < 16; ++j) {
                ulonglong2 ka = k16[2 * j], kb = k16[2 * j + 1];
                Sp[4 * j + 0] = fma2(w2, ka.x, Sp[4 * j + 0]);
                Sp[4 * j + 1] = fma2(w2, ka.y, Sp[4 * j + 1]);
                Sp[4 * j + 2] = fma2(w2, kb.x, Sp[4 * j + 2]);
                Sp[4 * j + 3] = fma2(w2, kb.y, Sp[4 * j + 3]);
            }
        } else {
            const float qu  = (qup[0] + qup[1]) + (qup[2] + qup[3]);
            const float kjv = k_sh[p][r];
            const float o   = aa * (c * phat) + qu * kjv;   // (q^T S_new)[j]
            Ob[t * CC + r] = o * g_sh[p][r];
            // S_hat^T[j][:] += (k_j/cn) * u
            const float kw = kjv * winv;
            const ull kw2 = pack2(kw, kw);
            const ulonglong2* u16 = (const ulonglong2*)u_sh;
#pragma unroll
            for (int j = 0; j < 16; ++j) {
                ulonglong2 ua = u16[2 * j], ub = u16[2 * j + 1];
                Sp[4 * j + 0] = fma2(kw2, ua.x, Sp[4 * j + 0]);
                Sp[4 * j + 1] = fma2(kw2, ua.y, Sp[4 * j + 1]);
                Sp[4 * j + 2] = fma2(kw2, ub.x, Sp[4 * j + 2]);
                Sp[4 * j + 3] = fma2(kw2, ub.y, Sp[4 * j + 3]);
            }
        }

        c = cn;
        if (c < 1e-10f) {
            const ull c2 = pack2(c, c);
#pragma unroll
            for (int j = 0; j < 64; ++j) Sp[j] = mul2(Sp[j], c2);
            c = 1.0f;
        }
        p ^= 1;
    }
}

// ===========================================================================
// Kernel 5: out = O @ Wo + bo   (M=16384, N=1024, K=128), f32x2 SGEMM
// ===========================================================================
__global__ __launch_bounds__(256) void out_gemm(
    const float* __restrict__ Wo, const float* __restrict__ bo,
    float* __restrict__ out)
{
    __shared__ __align__(16) float As2[16][256];
    __shared__ __align__(16) float Bs[16][128];

    const int row0 = blockIdx.x * 128;
    const int col0 = blockIdx.y * 128;
    const int tid  = threadIdx.x;
    const int tx   = tid & 15;
    const int ty   = tid >> 4;
    const int lr   = tid >> 2;
    const int lc   = (tid & 3) * 4;

    ull acc[8][4];
#pragma unroll
    for (int m = 0; m < 8; ++m)
#pragma unroll
        for (int n = 0; n < 4; ++n) acc[m][n] = 0ull;

    for (int k0 = 0; k0 < CC; k0 += 16) {
#pragma unroll
        for (int h = 0; h < 2; ++h) {
            int r = lr + h * 64;
            float4 a4 = *(const float4*)(g_O + (size_t)(row0 + r) * CC + k0 + lc);
            *(float2*)&As2[lc + 0][2 * r] = make_float2(a4.x, a4.x);
            *(float2*)&As2[lc + 1][2 * r] = make_float2(a4.y, a4.y);
            *(float2*)&As2[lc + 2][2 * r] = make_float2(a4.z, a4.z);
            *(float2*)&As2[lc + 3][2 * r] = make_float2(a4.w, a4.w);
        }
#pragma unroll
        for (int h = 0; h < 2; ++h) {
            int kk = (tid >> 5) + h * 8;
            int n  = (tid & 31) * 4;
            *(float4*)&Bs[kk][n] = *(const float4*)(Wo + (size_t)(k0 + kk) * DIMK + col0 + n);
        }
        __syncthreads();
#pragma unroll
        for (int kk = 0; kk < 16; ++kk) {
            const ulonglong2* ap = (const ulonglong2*)&As2[kk][2 * (ty * 8)];
            const ulonglong2* bp = (const ulonglong2*)&Bs[kk][tx * 8];
            ulonglong2 a01 = ap[0], a23 = ap[1], a45 = ap[2], a67 = ap[3];
            ulonglong2 b01 = bp[0], b23 = bp[1];
            ull ar[8] = {a01.x, a01.y, a23.x, a23.y, a45.x, a45.y, a67.x, a67.y};
            ull br[4] = {b01.x, b01.y, b23.x, b23.y};
#pragma unroll
            for (int m = 0; m < 8; ++m)
#pragma unroll
                for (int n = 0; n < 4; ++n)
                    acc[m][n] = fma2(ar[m], br[n], acc[m][n]);
        }
        __syncthreads();
    }

#pragma unroll
    for (int m = 0; m < 8; ++m) {
        int row = row0 + ty * 8 + m;
#pragma unroll
        for (int n = 0; n < 4; ++n) {
            int col = col0 + tx * 8 + 2 * n;
            float e0, e1; unpack2(acc[m][n], e0, e1);
            *(float2*)&out[(size_t)row * DIMK + col] =
                make_float2(e0 + bo[col], e1 + bo[col + 1]);
        }
    }
}

// ===========================================================================
extern "C" void kernel_launch(void* const* d_in, const int* in_sizes, int n_in,
                              void* d_out, int out_size)
{
    const float* x  = (const float*)d_in[0];
    const float* Wq = (const float*)d_in[1];  const float* bq = (const float*)d_in[2];
    const float* Wk = (const float*)d_in[3];  const float* bk = (const float*)d_in[4];
    const float* Wv = (const float*)d_in[5];  const float* bv = (const float*)d_in[6];
    const float* Wa = (const float*)d_in[7];  const float* ba = (const float*)d_in[8];
    const float* Wb = (const float*)d_in[9];  const float* bb = (const float*)d_in[10];
    const float* Wg = (const float*)d_in[11]; const float* bg = (const float*)d_in[12];
    const float* Wo = (const float*)d_in[13]; const float* bo = (const float*)d_in[14];
    float* out = (float*)d_out;

    proj_gemm<<<dim3(128, 4), 256>>>(x, Wq, Wk, Wv, Wg, bq, bk, bv, bg);
    ab_kernel<<<2048, 256>>>(x, Wa, ba, Wb, bb);
    knorm_kernel<<<2048, 256>>>();
    scan_kernel<<<BB, 256>>>();
    out_gemm<<<dim3(128, 8), 256>>>(Wo, bo, out);
}